// round 13
// baseline (speedup 1.0000x reference)
#include <cuda_runtime.h>

// CosmosUnpatcher3d — FINAL (best measured: 37.376 us; 6x-confirmed band
// 37.38-37.63 us across equivalent variants).
// One Haar IDWT level (2,24,9,256,256) -> T-slice -> (2,3,17,512,512).
// Combined tap c^3*sqrt(8) = 1 exactly, so each 2x2x2 output block is the
// 8-point Walsh-Hadamard transform of the 8 band values at that (t,h,w):
//   out[2t+pt-1, 2h+ph, 2w+pw] = sum_band (-1)^popcount(band & parity) * in[band]
//
// Design (optimal over a 12-round, 8-axis experiment matrix):
//  - one thread per input float2 per (b,ch,t,h): 8 coalesced band loads,
//    MLP=8, 32 regs -> ~80% achieved occupancy
//  - two register WHT-8 butterflies (24 FADD per 16 outputs)
//  - up to 4 coalesced float4 write-through stores (512B/warp full lines)
//  - exact grid (6912x256), no smem, no sync.
// Measured ceiling: 5.9TB/s sustained (73% DRAM-active) = mixed read/write
// HBM3e limit for this pattern; traffic irreducible at 220MB (zero reuse).
// Falsified axes: load policy (.cs/.cg), store policy (.cs), 16B loads,
// h-chunking, CTA granularity, persistent prefetch pipelining.

#define BAND_STRIDE2 (3 * 9 * 256 * 128)   // band stride in float2 units

__device__ __forceinline__ void wht8(const float v0, const float v1, const float v2,
                                     const float v3, const float v4, const float v5,
                                     const float v6, const float v7, float o[8]) {
    float a0 = v0 + v1, a1 = v0 - v1;
    float a2 = v2 + v3, a3 = v2 - v3;
    float a4 = v4 + v5, a5 = v4 - v5;
    float a6 = v6 + v7, a7 = v6 - v7;
    float b0 = a0 + a2, b2 = a0 - a2;
    float b1 = a1 + a3, b3 = a1 - a3;
    float b4 = a4 + a6, b6 = a4 - a6;
    float b5 = a5 + a7, b7 = a5 - a7;
    o[0] = b0 + b4; o[4] = b0 - b4;
    o[1] = b1 + b5; o[5] = b1 - b5;
    o[2] = b2 + b6; o[6] = b2 - b6;
    o[3] = b3 + b7; o[7] = b3 - b7;
}

__global__ __launch_bounds__(256)
void idwt_haar_kernel(const float* __restrict__ in, float* __restrict__ out) {
    int tid = blockIdx.x * 256 + threadIdx.x;
    // total threads = 2*3*9*256*128 = 1,769,472 (exact grid, no tail check)
    int wp = tid & 127;          // w-pair index [0,128)
    int h  = (tid >> 7) & 255;   // input h [0,256)
    int r  = tid >> 15;          // [0,54) = (b*3+ch)*9 + t
    int t  = r % 9;
    int bc = r / 9;              // b*3 + ch
    int b  = bc / 3;
    int ch = bc - 3 * b;

    // input base in float2 units
    int ibase2 = ((((b * 24 + ch) * 9 + t) << 16) + (h << 8) + (wp << 1)) >> 1;
    const float2* in2 = (const float2*)in;

    float2 v0 = in2[ibase2 + 0 * BAND_STRIDE2];
    float2 v1 = in2[ibase2 + 1 * BAND_STRIDE2];
    float2 v2 = in2[ibase2 + 2 * BAND_STRIDE2];
    float2 v3 = in2[ibase2 + 3 * BAND_STRIDE2];
    float2 v4 = in2[ibase2 + 4 * BAND_STRIDE2];
    float2 v5 = in2[ibase2 + 5 * BAND_STRIDE2];
    float2 v6 = in2[ibase2 + 6 * BAND_STRIDE2];
    float2 v7 = in2[ibase2 + 7 * BAND_STRIDE2];

    float x[8], y[8];
    wht8(v0.x, v1.x, v2.x, v3.x, v4.x, v5.x, v6.x, v7.x, x);
    wht8(v0.y, v1.y, v2.y, v3.y, v4.y, v5.y, v6.y, v7.y, y);

    // Output (2,3,17,512,512): t2 = 2t + pt - 1 (drop t2 < 0).
#pragma unroll
    for (int pt = 0; pt < 2; pt++) {
        int t2 = 2 * t + pt - 1;
        if (t2 < 0) continue;
#pragma unroll
        for (int ph = 0; ph < 2; ph++) {
            int p = pt * 4 + ph * 2;
            int obase = ((bc * 17 + t2) << 18) + (((h << 1) + ph) << 9) + (wp << 2);
            __stwt((float4*)(out + obase),
                   make_float4(x[p], x[p + 1], y[p], y[p + 1]));
        }
    }
}

extern "C" void kernel_launch(void* const* d_in, const int* in_sizes, int n_in,
                              void* d_out, int out_size) {
    const float* in = (const float*)d_in[0];
    float* out = (float*)d_out;
    // 1,769,472 threads / 256 = 6912 blocks
    idwt_haar_kernel<<<6912, 256>>>(in, out);
}

// round 14
// speedup vs baseline: 1.0129x; 1.0129x over previous
#include <cuda_runtime.h>

// CosmosUnpatcher3d: one Haar IDWT level (2,24,9,256,256) -> T-slice -> (2,3,17,512,512).
// Combined tap c^3*sqrt(8) = 1 exactly: each 2x2x2 output block is the 8-point
// Walsh-Hadamard transform of the 8 band values at that (t,h,w).
//
// R14 = confirmed-optimal body (32 regs, float2 loads, float4 __stwt stores,
// exact grid) with 512-thread blocks (3456 blocks, 4 CTA/SM) — the last
// untested cell on the block-size axis (128 neutral, 256 best, 512 here).
// Fewer/wider CTAs per SM -> lower cross-CTA L1tex queue contention (spr_max
// model: oe 8 -> 4 at equal warp count).

#define BAND_STRIDE2 (3 * 9 * 256 * 128)   // band stride in float2 units

__device__ __forceinline__ void wht8(const float v0, const float v1, const float v2,
                                     const float v3, const float v4, const float v5,
                                     const float v6, const float v7, float o[8]) {
    float a0 = v0 + v1, a1 = v0 - v1;
    float a2 = v2 + v3, a3 = v2 - v3;
    float a4 = v4 + v5, a5 = v4 - v5;
    float a6 = v6 + v7, a7 = v6 - v7;
    float b0 = a0 + a2, b2 = a0 - a2;
    float b1 = a1 + a3, b3 = a1 - a3;
    float b4 = a4 + a6, b6 = a4 - a6;
    float b5 = a5 + a7, b7 = a5 - a7;
    o[0] = b0 + b4; o[4] = b0 - b4;
    o[1] = b1 + b5; o[5] = b1 - b5;
    o[2] = b2 + b6; o[6] = b2 - b6;
    o[3] = b3 + b7; o[7] = b3 - b7;
}

__global__ __launch_bounds__(512)
void idwt_haar_kernel(const float* __restrict__ in, float* __restrict__ out) {
    int tid = blockIdx.x * 512 + threadIdx.x;
    // total threads = 2*3*9*256*128 = 1,769,472 (exact grid, no tail check)
    int wp = tid & 127;          // w-pair index [0,128)
    int h  = (tid >> 7) & 255;   // input h [0,256)
    int r  = tid >> 15;          // [0,54) = (b*3+ch)*9 + t
    int t  = r % 9;
    int bc = r / 9;              // b*3 + ch
    int b  = bc / 3;
    int ch = bc - 3 * b;

    // input base in float2 units
    int ibase2 = ((((b * 24 + ch) * 9 + t) << 16) + (h << 8) + (wp << 1)) >> 1;
    const float2* in2 = (const float2*)in;

    float2 v0 = in2[ibase2 + 0 * BAND_STRIDE2];
    float2 v1 = in2[ibase2 + 1 * BAND_STRIDE2];
    float2 v2 = in2[ibase2 + 2 * BAND_STRIDE2];
    float2 v3 = in2[ibase2 + 3 * BAND_STRIDE2];
    float2 v4 = in2[ibase2 + 4 * BAND_STRIDE2];
    float2 v5 = in2[ibase2 + 5 * BAND_STRIDE2];
    float2 v6 = in2[ibase2 + 6 * BAND_STRIDE2];
    float2 v7 = in2[ibase2 + 7 * BAND_STRIDE2];

    float x[8], y[8];
    wht8(v0.x, v1.x, v2.x, v3.x, v4.x, v5.x, v6.x, v7.x, x);
    wht8(v0.y, v1.y, v2.y, v3.y, v4.y, v5.y, v6.y, v7.y, y);

    // Output (2,3,17,512,512): t2 = 2t + pt - 1 (drop t2 < 0).
#pragma unroll
    for (int pt = 0; pt < 2; pt++) {
        int t2 = 2 * t + pt - 1;
        if (t2 < 0) continue;
#pragma unroll
        for (int ph = 0; ph < 2; ph++) {
            int p = pt * 4 + ph * 2;
            int obase = ((bc * 17 + t2) << 18) + (((h << 1) + ph) << 9) + (wp << 2);
            __stwt((float4*)(out + obase),
                   make_float4(x[p], x[p + 1], y[p], y[p + 1]));
        }
    }
}

extern "C" void kernel_launch(void* const* d_in, const int* in_sizes, int n_in,
                              void* d_out, int out_size) {
    const float* in = (const float*)d_in[0];
    float* out = (float*)d_out;
    // 1,769,472 threads / 512 = 3456 blocks
    idwt_haar_kernel<<<3456, 512>>>(in, out);
}